// round 17
// baseline (speedup 1.0000x reference)
#include <cuda_runtime.h>
#include <cuda_bf16.h>
#include <cstdint>

#define NN 512
#define DD 128
#define HH 128
#define PP (NN*NN)
#define EPSV 1e-6f

// ---------------- scratch (static device allocations; no cudaMalloc) ----------------
// Sequence: K1(ln) writes XH/XL (aliased in g_xn) -> split_w writes g_WH/g_WL ->
// K2(proj_mma) reads XH/XL + W planes, writes AH/AL/BH/BL ([d][k][i] bf16) + ogT (f32)
// -> K3(einsum_mma) reads planes via ldmatrix.trans, writes g_xn (f32 outT; XH/XL dead)
// -> K4(out_mma) reads g_xn + ogT, LN+gate, GEMM vs split W_out -> d_out.
__device__ float g_xn[(size_t)PP * DD];      // ln: bf16 XH|XL planes; einsum: f32 outT
__device__ float g_ogT[(size_t)HH * PP];     // [d][p]
// bf16 split planes, layout [d][k*N+i] (= [d][p], K-as-rows)
__device__ __nv_bfloat16 g_AH[(size_t)HH * PP];
__device__ __nv_bfloat16 g_AL[(size_t)HH * PP];
__device__ __nv_bfloat16 g_BH[(size_t)HH * PP];
__device__ __nv_bfloat16 g_BL[(size_t)HH * PP];
// weight planes, K-major transposed: [m][h][k], m: 0=Wl 1=Wr 2=Wlg 3=Wrg 4=Wog 5=Wout
__device__ __nv_bfloat16 g_WH[6 * DD * HH];
__device__ __nv_bfloat16 g_WL[6 * DD * HH];

__device__ __forceinline__ float sigmoidf_(float x) {
    return 1.0f / (1.0f + expf(-x));
}

// ---------------- warp-MMA helpers (base ISA) ----------------
__device__ __forceinline__ uint32_t smem_u32_(const void* p) {
    uint32_t a;
    asm("{ .reg .u64 t; cvta.to.shared.u64 t, %1; cvt.u32.u64 %0, t; }" : "=r"(a) : "l"(p));
    return a;
}
__device__ __forceinline__ void ldmx4_(uint32_t& r0, uint32_t& r1, uint32_t& r2,
                                       uint32_t& r3, uint32_t addr) {
    asm volatile("ldmatrix.sync.aligned.m8n8.x4.shared.b16 {%0,%1,%2,%3}, [%4];"
                 : "=r"(r0), "=r"(r1), "=r"(r2), "=r"(r3) : "r"(addr));
}
__device__ __forceinline__ void ldmx4t_(uint32_t& r0, uint32_t& r1, uint32_t& r2,
                                        uint32_t& r3, uint32_t addr) {
    asm volatile("ldmatrix.sync.aligned.m8n8.x4.trans.shared.b16 {%0,%1,%2,%3}, [%4];"
                 : "=r"(r0), "=r"(r1), "=r"(r2), "=r"(r3) : "r"(addr));
}
__device__ __forceinline__ void mma16816_(float* c, const uint32_t* a, uint32_t b0,
                                          uint32_t b1) {
    asm volatile(
        "mma.sync.aligned.m16n8k16.row.col.f32.bf16.bf16.f32 "
        "{%0,%1,%2,%3}, {%4,%5,%6,%7}, {%8,%9}, {%0,%1,%2,%3};"
        : "+f"(c[0]), "+f"(c[1]), "+f"(c[2]), "+f"(c[3])
        : "r"(a[0]), "r"(a[1]), "r"(a[2]), "r"(a[3]), "r"(b0), "r"(b1));
}
__device__ __forceinline__ void bf16split_(float v, unsigned& h, unsigned& l) {
    __nv_bfloat16 hb = __float2bfloat16_rn(v);
    __nv_bfloat16 lb = __float2bfloat16_rn(v - __bfloat162float(hb));
    h = __bfloat16_as_ushort(hb); l = __bfloat16_as_ushort(lb);
}

// ---------------- K1: layernorm over D=128, warp per row; emits bf16 hi/lo planes -----
__global__ void ln_kernel(const float* __restrict__ x,
                          const float* __restrict__ scale,
                          const float* __restrict__ bias) {
    int row = blockIdx.x * 8 + threadIdx.y;
    int lane = threadIdx.x;
    float4 v = reinterpret_cast<const float4*>(x + (size_t)row * DD)[lane];
    float s  = v.x + v.y + v.z + v.w;
    float sq = v.x*v.x + v.y*v.y + v.z*v.z + v.w*v.w;
    #pragma unroll
    for (int o = 16; o > 0; o >>= 1) {
        s  += __shfl_xor_sync(0xffffffffu, s, o);
        sq += __shfl_xor_sync(0xffffffffu, sq, o);
    }
    float mu = s * (1.0f / DD);
    float var = sq * (1.0f / DD) - mu * mu;
    float rstd = rsqrtf(var + EPSV);
    float4 sc = reinterpret_cast<const float4*>(scale)[lane];
    float4 bi = reinterpret_cast<const float4*>(bias)[lane];
    float o4[4];
    o4[0] = (v.x - mu) * rstd * sc.x + bi.x;
    o4[1] = (v.y - mu) * rstd * sc.y + bi.y;
    o4[2] = (v.z - mu) * rstd * sc.z + bi.z;
    o4[3] = (v.w - mu) * rstd * sc.w + bi.w;
    unsigned h[4], l[4];
    #pragma unroll
    for (int u = 0; u < 4; u++) bf16split_(o4[u], h[u], l[u]);
    __nv_bfloat16* XH = reinterpret_cast<__nv_bfloat16*>(g_xn);
    __nv_bfloat16* XL = XH + (size_t)PP * DD;
    size_t base = (size_t)row * DD + lane * 4;
    *reinterpret_cast<uint2*>(&XH[base]) = make_uint2(h[0] | (h[1] << 16), h[2] | (h[3] << 16));
    *reinterpret_cast<uint2*>(&XL[base]) = make_uint2(l[0] | (l[1] << 16), l[2] | (l[3] << 16));
}

// ---------------- split_w: W[k][h] f32 -> WT[h][k] bf16 hi/lo, all 6 matrices ----------
__global__ __launch_bounds__(256) void split_w(
    const float* __restrict__ Wl, const float* __restrict__ Wr,
    const float* __restrict__ Wlg, const float* __restrict__ Wrg,
    const float* __restrict__ Wog, const float* __restrict__ Wout) {
    const float* Ws[6] = {Wl, Wr, Wlg, Wrg, Wog, Wout};
    int m = blockIdx.x;
    const float* W = Ws[m];
    __shared__ float t[32][33];
    int tx = threadIdx.x & 31, ty = threadIdx.x >> 5;   // ty 0..7
    for (int bk = 0; bk < 4; bk++)
        for (int bh = 0; bh < 4; bh++) {
            __syncthreads();
            for (int r = ty; r < 32; r += 8)
                t[r][tx] = W[(bk*32 + r) * HH + bh*32 + tx];
            __syncthreads();
            for (int hr = ty; hr < 32; hr += 8) {
                float v = t[tx][hr];               // = W[bk*32+tx][bh*32+hr]
                unsigned hb, lb;
                bf16split_(v, hb, lb);
                size_t o = (size_t)m * DD * HH + (size_t)(bh*32 + hr) * DD + bk*32 + tx;
                g_WH[o] = __ushort_as_bfloat16((unsigned short)hb);
                g_WL[o] = __ushort_as_bfloat16((unsigned short)lb);
            }
        }
}

// ---------------- K2: proj on tensor cores; epilogue emits bf16 hi/lo planes ----------
// CTA: 128 p-rows x 64 h-cols; grid.z group: 0=(Wl,Wlg)->AH/AL, 1=(Wr,Wrg)->BH/BL,
// 2=(Wog)->ogT (f32). 8 warps: wm(4) x wh(2), warp tile 32p x 32h.
#define PM_PITCH 40
__global__ __launch_bounds__(256, 2) void proj_mma(
    const float* __restrict__ src_mask,
    const float* __restrict__ bl,  const float* __restrict__ br,
    const float* __restrict__ blg, const float* __restrict__ brg,
    const float* __restrict__ bog)
{
    __shared__ __align__(16) char sm_[40960];
    __nv_bfloat16* sXH = reinterpret_cast<__nv_bfloat16*>(sm_);
    __nv_bfloat16* sXL = sXH + 128 * PM_PITCH;
    __nv_bfloat16* sW  = sXL + 128 * PM_PITCH;     // [pm=mat*2+plane][64*PM_PITCH]
    uint32_t bXH = smem_u32_(sXH), bXL = smem_u32_(sXL), bW = smem_u32_(sW);

    int tid = threadIdx.x, wid = tid >> 5, lane = tid & 31;
    int wm = wid & 3, wh = wid >> 2;
    int p0 = blockIdx.x * 128, h0 = blockIdx.y * 64, grp = blockIdx.z;
    int m0 = (grp == 2) ? 4 : grp;
    int m1 = (grp == 2) ? 4 : grp + 2;

    const __nv_bfloat16* XH = reinterpret_cast<const __nv_bfloat16*>(g_xn);
    const __nv_bfloat16* XL = XH + (size_t)PP * DD;

    float acc[2][2][4][4] = {};   // [mat][mt][nt][4]

    for (int kk = 0; kk < DD; kk += 32) {
        __syncthreads();
        #pragma unroll
        for (int it = 0; it < 2; it++) {
            int idx = tid + it * 256;
            int r = idx >> 2, sg = idx & 3;
            size_t gg = (size_t)(p0 + r) * DD + kk + sg * 8;
            uint32_t so = (uint32_t)(r * PM_PITCH + sg * 8) * 2;
            *reinterpret_cast<uint4*>((char*)sXH + so) = *reinterpret_cast<const uint4*>(&XH[gg]);
            *reinterpret_cast<uint4*>((char*)sXL + so) = *reinterpret_cast<const uint4*>(&XL[gg]);
        }
        #pragma unroll
        for (int it = 0; it < 4; it++) {
            int idx = tid + it * 256;
            int pm = idx >> 8, rr2 = (idx >> 2) & 63, sg = idx & 3;
            int mat = pm >> 1, pl = pm & 1;
            int mg = mat ? m1 : m0;
            const __nv_bfloat16* src = (pl ? g_WL : g_WH) +
                (size_t)mg * DD * HH + (size_t)(h0 + rr2) * DD + kk + sg * 8;
            uint32_t so = (uint32_t)(pm * 64 * PM_PITCH + rr2 * PM_PITCH + sg * 8) * 2;
            *reinterpret_cast<uint4*>((char*)sW + so) = *reinterpret_cast<const uint4*>(src);
        }
        __syncthreads();

        #pragma unroll
        for (int ks = 0; ks < 2; ks++) {
            int k0 = ks * 16;
            uint32_t aH[2][4], aL[2][4];
            #pragma unroll
            for (int mt = 0; mt < 2; mt++) {
                int row = wm * 32 + mt * 16 + (lane & 15);
                int col = k0 + (lane >> 4) * 8;
                uint32_t off = (uint32_t)(row * PM_PITCH + col) * 2;
                ldmx4_(aH[mt][0], aH[mt][1], aH[mt][2], aH[mt][3], bXH + off);
                ldmx4_(aL[mt][0], aL[mt][1], aL[mt][2], aL[mt][3], bXL + off);
            }
            #pragma unroll
            for (int mat = 0; mat < 2; mat++) {
                if (mat == 1 && grp == 2) break;   // ogate group has one matrix
                uint32_t bH[4][2], bL[4][2];
                #pragma unroll
                for (int np = 0; np < 2; np++) {
                    int g8 = lane >> 3, r8 = lane & 7;
                    int nrow = wh * 32 + np * 16 + (g8 >> 1) * 8 + r8;
                    int col = k0 + (g8 & 1) * 8;
                    uint32_t offH = (uint32_t)((mat*2 + 0) * 64 * PM_PITCH + nrow * PM_PITCH + col) * 2;
                    uint32_t offL = (uint32_t)((mat*2 + 1) * 64 * PM_PITCH + nrow * PM_PITCH + col) * 2;
                    uint32_t r0, r1, r2, r3;
                    ldmx4_(r0, r1, r2, r3, bW + offH);
                    bH[np*2][0] = r0; bH[np*2][1] = r1; bH[np*2+1][0] = r2; bH[np*2+1][1] = r3;
                    ldmx4_(r0, r1, r2, r3, bW + offL);
                    bL[np*2][0] = r0; bL[np*2][1] = r1; bL[np*2+1][0] = r2; bL[np*2+1][1] = r3;
                }
                #pragma unroll
                for (int mt = 0; mt < 2; mt++)
                    #pragma unroll
                    for (int nt = 0; nt < 4; nt++) {
                        mma16816_(acc[mat][mt][nt], aH[mt], bH[nt][0], bH[nt][1]);
                        mma16816_(acc[mat][mt][nt], aH[mt], bL[nt][0], bL[nt][1]);
                        mma16816_(acc[mat][mt][nt], aL[mt], bH[nt][0], bH[nt][1]);
                    }
            }
        }
    }

    // epilogue
    const float* b0 = (grp == 0) ? bl : (grp == 1) ? br : bog;
    const float* b1 = (grp == 0) ? blg : brg;   // unused for grp==2
    __syncthreads();
    if (grp < 2) {
        uint32_t* stg = reinterpret_cast<uint32_t*>(sm_);   // [64][132]
        #pragma unroll
        for (int mt = 0; mt < 2; mt++) {
            int ib = wm * 32 + mt * 16 + (lane >> 2);
            int pA = p0 + ib, pB = p0 + ib + 8;
            float mA = src_mask[pA >> 9] * src_mask[pA & (NN - 1)];
            float mB = src_mask[pB >> 9] * src_mask[pB & (NN - 1)];
            #pragma unroll
            for (int nt = 0; nt < 4; nt++) {
                int jl = wh * 32 + nt * 8 + (lane & 3) * 2;
                int hg = h0 + jl;
                float b0a = b0[hg], b0b = b0[hg + 1], b1a = b1[hg], b1b = b1[hg + 1];
                float v00 = (acc[0][mt][nt][0] + b0a) * mA * sigmoidf_(acc[1][mt][nt][0] + b1a);
                float v01 = (acc[0][mt][nt][1] + b0b) * mA * sigmoidf_(acc[1][mt][nt][1] + b1b);
                float v10 = (acc[0][mt][nt][2] + b0a) * mB * sigmoidf_(acc[1][mt][nt][2] + b1a);
                float v11 = (acc[0][mt][nt][3] + b0b) * mB * sigmoidf_(acc[1][mt][nt][3] + b1b);
                unsigned h_, l_;
                bf16split_(v00, h_, l_); stg[jl * 132 + ib]           = h_ | (l_ << 16);
                bf16split_(v01, h_, l_); stg[(jl + 1) * 132 + ib]     = h_ | (l_ << 16);
                bf16split_(v10, h_, l_); stg[jl * 132 + ib + 8]       = h_ | (l_ << 16);
                bf16split_(v11, h_, l_); stg[(jl + 1) * 132 + ib + 8] = h_ | (l_ << 16);
            }
        }
        __syncthreads();
        __nv_bfloat16* dH = (grp == 0) ? g_AH : g_BH;
        __nv_bfloat16* dL = (grp == 0) ? g_AL : g_BL;
        for (int idx = tid; idx < 64 * 32; idx += 256) {
            int row = idx >> 5, seg = idx & 31;
            uint32_t w0 = stg[row * 132 + seg*4];
            uint32_t w1 = stg[row * 132 + seg*4 + 1];
            uint32_t w2 = stg[row * 132 + seg*4 + 2];
            uint32_t w3 = stg[row * 132 + seg*4 + 3];
            uint2 hv = make_uint2((w0 & 0xffffu) | (w1 << 16), (w2 & 0xffffu) | (w3 << 16));
            uint2 lv = make_uint2((w0 >> 16) | (w1 & 0xffff0000u), (w2 >> 16) | (w3 & 0xffff0000u));
            size_t o = (size_t)(h0 + row) * PP + p0 + seg * 4;
            *reinterpret_cast<uint2*>(&dH[o]) = hv;
            *reinterpret_cast<uint2*>(&dL[o]) = lv;
        }
    } else {
        float* stage = reinterpret_cast<float*>(sm_);   // [64][132]
        #pragma unroll
        for (int mt = 0; mt < 2; mt++) {
            int ib = wm * 32 + mt * 16 + (lane >> 2);
            #pragma unroll
            for (int nt = 0; nt < 4; nt++) {
                int jl = wh * 32 + nt * 8 + (lane & 3) * 2;
                int hg = h0 + jl;
                float b0a = b0[hg], b0b = b0[hg + 1];
                stage[jl * 132 + ib]           = sigmoidf_(acc[0][mt][nt][0] + b0a);
                stage[(jl + 1) * 132 + ib]     = sigmoidf_(acc[0][mt][nt][1] + b0b);
                stage[jl * 132 + ib + 8]       = sigmoidf_(acc[0][mt][nt][2] + b0a);
                stage[(jl + 1) * 132 + ib + 8] = sigmoidf_(acc[0][mt][nt][3] + b0b);
            }
        }
        __syncthreads();
        for (int idx = tid; idx < 64 * 32; idx += 256) {
            int row = idx >> 5, seg = idx & 31;
            float4 v = *reinterpret_cast<float4*>(&stage[row * 132 + seg * 4]);
            *reinterpret_cast<float4*>(&g_ogT[(size_t)(h0 + row) * PP + p0 + seg * 4]) = v;
        }
    }
}

// ---------------- K3: triangle einsum via mma.sync; K-as-rows planes + ldmatrix.trans --
// out[d][i][j] = sum_k AH/AL[d][k][i] * BH/BL[d][k][j]   (unchanged, passing)
#define EPITCH 136
__global__ __launch_bounds__(256, 2) void einsum_mma() {
    __shared__ __align__(16) __nv_bfloat16 sAH[32 * EPITCH];
    __shared__ __align__(16) __nv_bfloat16 sAL[32 * EPITCH];
    __shared__ __align__(16) __nv_bfloat16 sBH[32 * EPITCH];
    __shared__ __align__(16) __nv_bfloat16 sBL[32 * EPITCH];
    int tid = threadIdx.x, wid = tid >> 5, lane = tid & 31;
    int wm = wid & 3, wn = wid >> 2;
    int j0 = blockIdx.x * 128, i0 = blockIdx.y * 128, d = blockIdx.z;

    const __nv_bfloat16* gsrc[4] = {
        g_AH + (size_t)d * PP + i0, g_AL + (size_t)d * PP + i0,
        g_BH + (size_t)d * PP + j0, g_BL + (size_t)d * PP + j0};
    char* sdst[4] = {(char*)sAH, (char*)sAL, (char*)sBH, (char*)sBL};

    uint32_t bAH = smem_u32_(sAH), bAL = smem_u32_(sAL);
    uint32_t bBH = smem_u32_(sBH), bBL = smem_u32_(sBL);

    float acc[2][8][4] = {};

    for (int kk = 0; kk < NN; kk += 32) {
        __syncthreads();
        #pragma unroll
        for (int pl = 0; pl < 4; pl++) {
            #pragma unroll
            for (int half = 0; half < 2; half++) {
                int rem = half * 256 + tid;
                int r = rem >> 4, sg = rem & 15;
                uint32_t so = (uint32_t)(r * EPITCH + sg * 8) * 2;
                *reinterpret_cast<uint4*>(sdst[pl] + so) =
                    *reinterpret_cast<const uint4*>(gsrc[pl] + (size_t)(kk + r) * NN + sg * 8);
            }
        }
        __syncthreads();

        #pragma unroll
        for (int ks = 0; ks < 2; ks++) {
            int k0 = ks * 16;
            uint32_t aH[2][4], aL[2][4];
            #pragma unroll
            for (int mt = 0; mt < 2; mt++) {
                int m0 = wm * 32 + mt * 16;
                int row = k0 + ((lane >> 4) << 3) + (lane & 7);
                int col = m0 + (((lane >> 3) & 1) << 3);
                uint32_t off = (uint32_t)(row * EPITCH + col) * 2;
                ldmx4t_(aH[mt][0], aH[mt][1], aH[mt][2], aH[mt][3], bAH + off);
                ldmx4t_(aL[mt][0], aL[mt][1], aL[mt][2], aL[mt][3], bAL + off);
            }
            uint32_t bH[8][2], bL[8][2];
            #pragma unroll
            for (int np = 0; np < 4; np++) {
                int n0 = wn * 64 + np * 16;
                int row = k0 + (((lane >> 3) & 1) << 3) + (lane & 7);
                int col = n0 + ((lane >> 4) << 3);
                uint32_t off = (uint32_t)(row * EPITCH + col) * 2;
                uint32_t r0, r1, r2, r3;
                ldmx4t_(r0, r1, r2, r3, bBH + off);
                bH[np*2][0] = r0; bH[np*2][1] = r1; bH[np*2+1][0] = r2; bH[np*2+1][1] = r3;
                ldmx4t_(r0, r1, r2, r3, bBL + off);
                bL[np*2][0] = r0; bL[np*2][1] = r1; bL[np*2+1][0] = r2; bL[np*2+1][1] = r3;
            }
            #pragma unroll
            for (int mt = 0; mt < 2; mt++)
                #pragma unroll
                for (int nt = 0; nt < 8; nt++) {
                    mma16816_(acc[mt][nt], aH[mt], bH[nt][0], bH[nt][1]);
                    mma16816_(acc[mt][nt], aH[mt], bL[nt][0], bL[nt][1]);
                    mma16816_(acc[mt][nt], aL[mt], bH[nt][0], bH[nt][1]);
                }
        }
    }

    float* O = g_xn + (size_t)d * PP;
    #pragma unroll
    for (int mt = 0; mt < 2; mt++) {
        int ib = i0 + wm * 32 + mt * 16 + (lane >> 2);
        #pragma unroll
        for (int nt = 0; nt < 8; nt++) {
            int jb = j0 + wn * 64 + nt * 8 + (lane & 3) * 2;
            *reinterpret_cast<float2*>(&O[(size_t)ib * NN + jb]) =
                make_float2(acc[mt][nt][0], acc[mt][nt][1]);
            *reinterpret_cast<float2*>(&O[(size_t)(ib + 8) * NN + jb]) =
                make_float2(acc[mt][nt][2], acc[mt][nt][3]);
        }
    }
}

// ---------------- K4: out-LN * ogate + W_out GEMM on tensor cores ----------------------
// CTA: 32 p-rows. Phase 1: stage f32 [128d][32p], LN over d, gate. Phase 2: per-16k
// chunk, bf16-split activations + W_out^T planes, 3-pass mma. 8 warps: wm(2) x wn(4).
#define OM_PITCH 24
__global__ __launch_bounds__(256, 4) void out_mma(
    const float* __restrict__ onscale, const float* __restrict__ onbias,
    const float* __restrict__ bout, float* __restrict__ out)
{
    __shared__ __align__(16) char smem_[16384 + 15360];
    float* sh = reinterpret_cast<float*>(smem_);                    // [128][32] f32
    char* plbase = smem_ + 16384;
    __nv_bfloat16* sAH = reinterpret_cast<__nv_bfloat16*>(plbase);  // [32][24]
    __nv_bfloat16* sAL = sAH + 32 * OM_PITCH;
    __nv_bfloat16* sWH = sAL + 32 * OM_PITCH;                       // [128][24]
    __nv_bfloat16* sWL = sWH + 128 * OM_PITCH;
    float* red_s = reinterpret_cast<float*>(plbase);                // [8][32] (reuse)
    float* red_q = red_s + 256;
    uint32_t bA0 = smem_u32_(sAH), bA1 = smem_u32_(sAL);
    uint32_t bW0 = smem_u32_(sWH), bW1 = smem_u32_(sWL);

    int tid = threadIdx.x, wid = tid >> 5, lane = tid & 31;
    int wm = wid & 1, wn = wid >> 1;   // warp tile: 16p x 32c
    int p0 = blockIdx.x * 32;

    // phase 1: stage, LN over d, gate
    for (int t = tid; t < 128 * 32; t += 256) {
        int dd = t >> 5, r = t & 31;
        sh[dd*32 + r] = g_xn[(size_t)dd * PP + p0 + r];
    }
    __syncthreads();
    int r = tid & 31, q = tid >> 5;   // q 0..7, 16 d's each
    float s = 0.f, sq = 0.f;
    #pragma unroll
    for (int u = 0; u < 16; u++) {
        float v = sh[(q*16 + u)*32 + r];
        s += v; sq += v*v;
    }
    red_s[q*32 + r] = s; red_q[q*32 + r] = sq;
    __syncthreads();
    float st = 0.f, sqt = 0.f;
    #pragma unroll
    for (int u = 0; u < 8; u++) { st += red_s[u*32 + r]; sqt += red_q[u*32 + r]; }
    float mu = st * (1.0f / HH);
    float rstd = rsqrtf(sqt * (1.0f / HH) - mu*mu + EPSV);
    #pragma unroll
    for (int u = 0; u < 16; u++) {
        int dd = q*16 + u;
        float v = sh[dd*32 + r];
        float g = g_ogT[(size_t)dd * PP + p0 + r];
        sh[dd*32 + r] = ((v - mu) * rstd * onscale[dd] + onbias[dd]) * g;
    }

    // phase 2: GEMM out[p][c] = sum_d act[p][d] * Wout[d][c], bf16 hi/lo 3-pass
    const __nv_bfloat16* WoH = g_WH + (size_t)5 * DD * HH;
    const __nv_bfloat16* WoL = g_WL + (size_t)5 * DD * HH;
    float acc[4][4] = {};
    for (int kk = 0; kk < DD; kk += 16) {
        __syncthreads();   // also guards red_s reuse on first iteration
        // A planes: 32p x 16d split from sh
        for (int idx = tid; idx < 32 * 16; idx += 256) {
            int p = idx >> 4, dd = idx & 15;
            float v = sh[(kk + dd)*32 + p];
            unsigned h_, l_;
            bf16split_(v, h_, l_);
            sAH[p*OM_PITCH + dd] = __ushort_as_bfloat16((unsigned short)h_);
            sAL[p*OM_PITCH + dd] = __ushort_as_bfloat16((unsigned short)l_);
        }
        // B planes: 128c x 16d from pre-split WoutT
        for (int idx = tid; idx < 128 * 2; idx += 256) {
            int c = idx >> 1, sg = idx & 1;
            size_t go = (size_t)c * DD + kk + sg * 8;
            uint32_t so = (uint32_t)(c * OM_PITCH + sg * 8) * 2;
            *reinterpret_cast<uint4*>((char*)sWH + so) = *reinterpret_cast<const uint4*>(&WoH[go]);
            *reinterpret_cast<uint4*>((char*)sWL + so) = *reinterpret_cast<const uint4*>(&WoL[go]);
        }
        __syncthreads();

        uint32_t aH[4], aL[4];
        {
            int row = wm * 16 + (lane & 15);
            int col = (lane >> 4) * 8;
            uint32_t off = (uint32_t)(row * OM_PITCH + col) * 2;
            ldmx4_(aH[0], aH[1], aH[2], aH[3], bA0 + off);
            ldmx4_(aL[0], aL[1], aL[2], aL[3], bA1 + off);
        }
        uint32_t bH[4][2], bL[4][2];
        #pragma unroll
        for (int np = 0; np < 2; np++) {
            int g8 = lane >> 3, r8 = lane & 7;
            int nrow = wn * 32 + np * 16 + (g8 >> 1) * 8 + r8;
            int col = (g8 & 1) * 8;
            uint32_t off = (uint32_t)(nrow * OM_PITCH + col) * 2;
            uint32_t r0, r1, r2, r3;
            ldmx4_(r0, r1, r2, r3, bW0 + off);
            bH[np*2][0] = r0; bH[np*2][1] = r1; bH[np*2+1][0] = r2; bH[np*2+1][1] = r3;
            ldmx4_(r0, r1, r2, r3, bW1 + off);
            bL[np*2][0] = r0; bL[np*2][1] = r1; bL[np*2+1][0] = r2; bL[np*2+1][1] = r3;
        }
        #pragma unroll
        for (int nt = 0; nt < 4; nt++) {
            mma16816_(acc[nt], aH, bH[nt][0], bH[nt][1]);
            mma16816_(acc[nt], aH, bL[nt][0], bL[nt][1]);
            mma16816_(acc[nt], aL, bH[nt][0], bH[nt][1]);
        }
    }

    // epilogue: + bias, write [p][c]
    int ibA = p0 + wm * 16 + (lane >> 2);
    #pragma unroll
    for (int nt = 0; nt < 4; nt++) {
        int c = wn * 32 + nt * 8 + (lane & 3) * 2;
        float b0 = bout[c], b1 = bout[c + 1];
        *reinterpret_cast<float2*>(&out[(size_t)ibA * DD + c]) =
            make_float2(acc[nt][0] + b0, acc[nt][1] + b1);
        *reinterpret_cast<float2*>(&out[(size_t)(ibA + 8) * DD + c]) =
            make_float2(acc[nt][2] + b0, acc[nt][3] + b1);
    }
}

// ---------------- launch ----------------
extern "C" void kernel_launch(void* const* d_in, const int* in_sizes, int n_in,
                              void* d_out, int out_size) {
    const float* x        = (const float*)d_in[0];
    const float* src_mask = (const float*)d_in[1];
    const float* nscale   = (const float*)d_in[2];
    const float* nbias    = (const float*)d_in[3];
    const float* Wl       = (const float*)d_in[4];
    const float* bl       = (const float*)d_in[5];
    const float* Wr       = (const float*)d_in[6];
    const float* br       = (const float*)d_in[7];
    const float* Wlg      = (const float*)d_in[8];
    const float* blg      = (const float*)d_in[9];
    const float* Wrg      = (const float*)d_in[10];
    const float* brg      = (const float*)d_in[11];
    const float* Wog      = (const float*)d_in[12];
    const float* bog      = (const float*)d_in[13];
    const float* onscale  = (const float*)d_in[14];
    const float* onbias   = (const float*)d_in[15];
    const float* Wout     = (const float*)d_in[16];
    const float* bout     = (const float*)d_in[17];
    float* out = (float*)d_out;

    ln_kernel<<<PP / 8, dim3(32, 8)>>>(x, nscale, nbias);
    split_w<<<6, 256>>>(Wl, Wr, Wlg, Wrg, Wog, Wout);
    proj_mma<<<dim3(PP / 128, 2, 3), 256>>>(src_mask, bl, br, blg, brg, bog);
    einsum_mma<<<dim3(NN / 128, NN / 128, HH), 256>>>();
    out_mma<<<PP / 32, 256>>>(onscale, onbias, bout, out);
}